// round 12
// baseline (speedup 1.0000x reference)
#include <cuda_runtime.h>
#include <cuda_bf16.h>

#define VOCAB  32000
#define NLABEL 16
#define NSTATE 64
#define BATCH  512
#define MAXLEN 512

typedef unsigned long long ull;

// Packed f32x2 ops (sm_103a; SASS FFMA2 — PTX-only path).
#define FMA2(d, a, b, c) \
    asm("fma.rn.f32x2 %0, %1, %2, %3;" : "=l"(d) : "l"(a), "l"(b), "l"(c))
#define ADD2(d, a, b) \
    asm("add.rn.f32x2 %0, %1, %2;" : "=l"(d) : "l"(a), "l"(b))

// Precomputed tables (device globals: no allocation allowed).
// g_Tpack float layout: Texp[r][i] stored at (i>>1)*128 + r*2 + (i&1).
// As 8-byte pairs: ull index jv*64 + r = (Texp[r][2jv], Texp[r][2jv+1]).
__device__ __align__(16) float g_Tpack[NSTATE * NSTATE];
__device__ float g_Oexp[NLABEL * NSTATE];   // [l*64 + s] = softmax(output[l,:])[s]
__device__ float g_lse [VOCAB];             // logsumexp(emb[v,:])

// ---------------------------------------------------------------------------
// Fused prep: blocks [0,40) do row-softmax (2 rows/block: 64+16 rows total);
// blocks [40, 40+VOCAB/4) do per-vocab-row logsumexp (4 rows/block).
// ---------------------------------------------------------------------------
__global__ void prep_all_kernel(const float* __restrict__ transition,
                                const float* __restrict__ output,
                                const float* __restrict__ emb) {
    const int blk = blockIdx.x;
    if (blk < 40) {
        const int half = threadIdx.x >> 6;     // which row in this block
        const int i    = threadIdx.x & 63;     // state index within row
        const int r    = blk * 2 + half;       // global row 0..79
        const float* src = (r < NSTATE) ? (transition + r * NSTATE)
                                        : (output + (r - NSTATE) * NSTATE);
        float v = src[i];

        __shared__ float shm[4];
        __shared__ float shs[4];

        float m = v;
        #pragma unroll
        for (int d = 16; d; d >>= 1) m = fmaxf(m, __shfl_xor_sync(0xffffffffu, m, d));
        if ((threadIdx.x & 31) == 0) shm[threadIdx.x >> 5] = m;
        __syncthreads();
        m = fmaxf(shm[half * 2], shm[half * 2 + 1]);

        float e = expf(v - m);
        float s = e;
        #pragma unroll
        for (int d = 16; d; d >>= 1) s += __shfl_xor_sync(0xffffffffu, s, d);
        if ((threadIdx.x & 31) == 0) shs[threadIdx.x >> 5] = s;
        __syncthreads();
        s = shs[half * 2] + shs[half * 2 + 1];

        const float val = e / s;
        if (r < NSTATE) g_Tpack[(i >> 1) * 128 + r * 2 + (i & 1)] = val;
        else            g_Oexp[(r - NSTATE) * NSTATE + i] = val;
    } else {
        const int gw   = (blk - 40) * 4 + (threadIdx.x >> 5);
        const int lane = threadIdx.x & 31;
        if (gw >= VOCAB) return;
        const float* row = emb + gw * NSTATE;
        float s = expf(row[lane]) + expf(row[lane + 32]);
        #pragma unroll
        for (int d = 16; d; d >>= 1) s += __shfl_xor_sync(0xffffffffu, s, d);
        if (lane == 0) g_lse[gw] = logf(s);
    }
}

// ---------------------------------------------------------------------------
// Main: ONE WARP per TWO batch elements (ILP over independent recurrences).
// Lane l owns states 2l, 2l+1 of BOTH batches. The per-batch step body is
// VERBATIM the 96.7us champion; the two copies are independent so the
// scheduler interleaves their FFMA2/LDS/MUFU streams, hiding each chain in
// the other's stalls. TA/TB transition registers are SHARED (same matrix).
// Uniform t<L guards handle unequal lengths; one __syncwarp per round.
// ---------------------------------------------------------------------------
__global__ void __launch_bounds__(32) hmm_forward_kernel(
    const int*   __restrict__ sentences,
    const int*   __restrict__ length,
    const float* __restrict__ emb,
    float*       __restrict__ out)
{
    const int lane = threadIdx.x;
    const int bA   = blockIdx.x * 2;
    const int bB   = bA + 1;

    __shared__ __align__(16) float GA[2][NSTATE];
    __shared__ __align__(16) float GB[2][NSTATE];
    __shared__ int tokA[MAXLEN + 3];
    __shared__ int tokB[MAXLEN + 3];

    const int  LA = length[bA];
    const int  LB = length[bB];
    const int  LmA = LA - 1, LmB = LB - 1;
    const int* sentA = sentences + bA * MAXLEN;
    const int* sentB = sentences + bB * MAXLEN;

    // Stage tokens pre-clamped.
    for (int i = lane; i < LA + 3; i += 32) tokA[i] = __ldg(&sentA[min(i, LmA)]);
    for (int i = lane; i < LB + 3; i += 32) tokB[i] = __ldg(&sentB[min(i, LmB)]);

    // Transition rows for states 2*lane, 2*lane+1 (shared by both batches).
    ull TA[NSTATE / 2], TB[NSTATE / 2];
    {
        const ulonglong2* Tp = reinterpret_cast<const ulonglong2*>(g_Tpack);
        #pragma unroll
        for (int jv = 0; jv < NSTATE / 2; ++jv) {
            const ulonglong2 p = __ldg(&Tp[jv * 32 + lane]);
            TA[jv] = p.x;
            TB[jv] = p.y;
        }
    }

    // ---- t = 0 for both batches ----
    {
        const float2 rw0A = *reinterpret_cast<const float2*>(&emb[__ldg(&sentA[0]) * NSTATE + 2 * lane]);
        const float2 rw0B = *reinterpret_cast<const float2*>(&emb[__ldg(&sentB[0]) * NSTATE + 2 * lane]);
        *reinterpret_cast<float2*>(&GA[0][2 * lane]) = make_float2(__expf(rw0A.x), __expf(rw0A.y));
        *reinterpret_cast<float2*>(&GB[0][2 * lane]) = make_float2(__expf(rw0B.x), __expf(rw0B.y));
    }
    __syncwarp();

    // 3-deep emission prefetch per batch.
    float2 rA1 = *reinterpret_cast<const float2*>(&emb[tokA[1] * NSTATE + 2 * lane]);
    float2 rA2 = *reinterpret_cast<const float2*>(&emb[tokA[2] * NSTATE + 2 * lane]);
    float2 rA3 = *reinterpret_cast<const float2*>(&emb[tokA[3] * NSTATE + 2 * lane]);
    float2 rB1 = *reinterpret_cast<const float2*>(&emb[tokB[1] * NSTATE + 2 * lane]);
    float2 rB2 = *reinterpret_cast<const float2*>(&emb[tokB[2] * NSTATE + 2 * lane]);
    float2 rB3 = *reinterpret_cast<const float2*>(&emb[tokB[3] * NSTATE + 2 * lane]);

    float offA = 0.f, offB = 0.f;
    int   bufA = 0,  bufB = 0;
    const int Lmax = max(LA, LB);

    for (int t = 1; t < Lmax; ++t) {
        if (t < LA) {   // ---- champion step body, batch A ----
            float eA = __expf(rA1.x);
            float eB = __expf(rA1.y);
            rA1 = rA2; rA2 = rA3;
            rA3 = *reinterpret_cast<const float2*>(&emb[tokA[t + 3] * NSTATE + 2 * lane]);

            if ((t & 63) == 0) {
                const float g0 = GA[bufA][0];
                float c;
                asm("rcp.approx.f32 %0, %1;" : "=f"(c) : "f"(g0));
                eA *= c; eB *= c;
                offA += __logf(g0);
            }

            const ulonglong2* Gv = reinterpret_cast<const ulonglong2*>(GA[bufA]);
            ull a0 = 0ull, a1 = 0ull, b0 = 0ull, b1 = 0ull;
            #pragma unroll
            for (int jv = 0; jv < 16; ++jv) {
                const ulonglong2 g = Gv[jv];
                FMA2(a0, TA[2 * jv + 0], g.x, a0);
                FMA2(b0, TB[2 * jv + 0], g.x, b0);
                FMA2(a1, TA[2 * jv + 1], g.y, a1);
                FMA2(b1, TB[2 * jv + 1], g.y, b1);
            }
            ull as, bs;
            ADD2(as, a0, a1);
            ADD2(bs, b0, b1);
            float alo, ahi, blo, bhi;
            asm("mov.b64 {%0, %1}, %2;" : "=f"(alo), "=f"(ahi) : "l"(as));
            asm("mov.b64 {%0, %1}, %2;" : "=f"(blo), "=f"(bhi) : "l"(bs));
            bufA ^= 1;
            *reinterpret_cast<float2*>(&GA[bufA][2 * lane]) =
                make_float2((alo + ahi) * eA, (blo + bhi) * eB);
        }

        if (t < LB) {   // ---- champion step body, batch B ----
            float eA = __expf(rB1.x);
            float eB = __expf(rB1.y);
            rB1 = rB2; rB2 = rB3;
            rB3 = *reinterpret_cast<const float2*>(&emb[tokB[t + 3] * NSTATE + 2 * lane]);

            if ((t & 63) == 0) {
                const float g0 = GB[bufB][0];
                float c;
                asm("rcp.approx.f32 %0, %1;" : "=f"(c) : "f"(g0));
                eA *= c; eB *= c;
                offB += __logf(g0);
            }

            const ulonglong2* Gv = reinterpret_cast<const ulonglong2*>(GB[bufB]);
            ull a0 = 0ull, a1 = 0ull, b0 = 0ull, b1 = 0ull;
            #pragma unroll
            for (int jv = 0; jv < 16; ++jv) {
                const ulonglong2 g = Gv[jv];
                FMA2(a0, TA[2 * jv + 0], g.x, a0);
                FMA2(b0, TB[2 * jv + 0], g.x, b0);
                FMA2(a1, TA[2 * jv + 1], g.y, a1);
                FMA2(b1, TB[2 * jv + 1], g.y, b1);
            }
            ull as, bs;
            ADD2(as, a0, a1);
            ADD2(bs, b0, b1);
            float alo, ahi, blo, bhi;
            asm("mov.b64 {%0, %1}, %2;" : "=f"(alo), "=f"(ahi) : "l"(as));
            asm("mov.b64 {%0, %1}, %2;" : "=f"(blo), "=f"(bhi) : "l"(bs));
            bufB ^= 1;
            *reinterpret_cast<float2*>(&GB[bufB][2 * lane]) =
                make_float2((alo + ahi) * eA, (blo + bhi) * eB);
        }

        __syncwarp();
    }

    // ---- emission-normalizer sums ----
    float SA = 0.f, SB = 0.f;
    for (int i = lane; i < LA; i += 32) SA += __ldg(&g_lse[tokA[i]]);
    for (int i = lane; i < LB; i += 32) SB += __ldg(&g_lse[tokB[i]]);
    #pragma unroll
    for (int d = 16; d; d >>= 1) {
        SA += __shfl_xor_sync(0xffffffffu, SA, d);
        SB += __shfl_xor_sync(0xffffffffu, SB, d);
    }

    // ---- readout: lanes 0..15, one label each, both batches ----
    if (lane < NLABEL) {
        const float* O = g_Oexp + lane * NSTATE;
        {
            const float* Gf = GA[bufA];
            float a0 = 0.f, a1 = 0.f, a2 = 0.f, a3 = 0.f;
            #pragma unroll
            for (int j4 = 0; j4 < NSTATE / 4; ++j4) {
                a0 = fmaf(__ldg(&O[4 * j4 + 0]), Gf[4 * j4 + 0], a0);
                a1 = fmaf(__ldg(&O[4 * j4 + 1]), Gf[4 * j4 + 1], a1);
                a2 = fmaf(__ldg(&O[4 * j4 + 2]), Gf[4 * j4 + 2], a2);
                a3 = fmaf(__ldg(&O[4 * j4 + 3]), Gf[4 * j4 + 3], a3);
            }
            out[bA * NLABEL + lane] = __logf((a0 + a1) + (a2 + a3)) + offA - SA;
        }
        {
            const float* Gf = GB[bufB];
            float a0 = 0.f, a1 = 0.f, a2 = 0.f, a3 = 0.f;
            #pragma unroll
            for (int j4 = 0; j4 < NSTATE / 4; ++j4) {
                a0 = fmaf(__ldg(&O[4 * j4 + 0]), Gf[4 * j4 + 0], a0);
                a1 = fmaf(__ldg(&O[4 * j4 + 1]), Gf[4 * j4 + 1], a1);
                a2 = fmaf(__ldg(&O[4 * j4 + 2]), Gf[4 * j4 + 2], a2);
                a3 = fmaf(__ldg(&O[4 * j4 + 3]), Gf[4 * j4 + 3], a3);
            }
            out[bB * NLABEL + lane] = __logf((a0 + a1) + (a2 + a3)) + offB - SB;
        }
    }
}

// ---------------------------------------------------------------------------
extern "C" void kernel_launch(void* const* d_in, const int* in_sizes, int n_in,
                              void* d_out, int out_size) {
    const int*   sentences  = nullptr;
    const int*   length     = nullptr;
    const float* emb        = nullptr;
    const float* transition = nullptr;
    const float* output     = nullptr;

    for (int i = 0; i < n_in; ++i) {
        switch (in_sizes[i]) {
            case BATCH * MAXLEN:   sentences  = (const int*)  d_in[i]; break;
            case BATCH:            length     = (const int*)  d_in[i]; break;
            case VOCAB * NSTATE:   emb        = (const float*)d_in[i]; break;
            case NSTATE * NSTATE:  transition = (const float*)d_in[i]; break;
            case NLABEL * NSTATE:  output     = (const float*)d_in[i]; break;
            default: break;
        }
    }

    prep_all_kernel<<<40 + VOCAB / 4, 128>>>(transition, output, emb);
    hmm_forward_kernel<<<BATCH / 2, 32>>>(sentences, length, emb, (float*)d_out);
}

// round 13
// speedup vs baseline: 7.2207x; 7.2207x over previous
#include <cuda_runtime.h>
#include <cuda_bf16.h>

#define VOCAB  32000
#define NLABEL 16
#define NSTATE 64
#define BATCH  512
#define MAXLEN 512

typedef unsigned long long ull;

// Packed f32x2 ops (sm_103a; SASS FFMA2 — PTX-only path).
#define FMA2(d, a, b, c) \
    asm("fma.rn.f32x2 %0, %1, %2, %3;" : "=l"(d) : "l"(a), "l"(b), "l"(c))
#define ADD2(d, a, b) \
    asm("add.rn.f32x2 %0, %1, %2;" : "=l"(d) : "l"(a), "l"(b))

// Precomputed tables (device globals: no allocation allowed).
// g_Tpack float layout: Texp[r][i] stored at (i>>1)*128 + r*2 + (i&1).
// As 8-byte pairs: ull index jv*64 + r = (Texp[r][2jv], Texp[r][2jv+1]).
__device__ __align__(16) float g_Tpack[NSTATE * NSTATE];
__device__ float g_Oexp[NLABEL * NSTATE];   // [l*64 + s] = softmax(output[l,:])[s]
__device__ float g_lse [VOCAB];             // logsumexp(emb[v,:])

// ---------------------------------------------------------------------------
// Fused prep: blocks [0,40) do row-softmax (2 rows/block: 64+16 rows total);
// blocks [40, 40+VOCAB/4) do per-vocab-row logsumexp (4 rows/block).
// ---------------------------------------------------------------------------
__global__ void prep_all_kernel(const float* __restrict__ transition,
                                const float* __restrict__ output,
                                const float* __restrict__ emb) {
    const int blk = blockIdx.x;
    if (blk < 40) {
        const int half = threadIdx.x >> 6;     // which row in this block
        const int i    = threadIdx.x & 63;     // state index within row
        const int r    = blk * 2 + half;       // global row 0..79
        const float* src = (r < NSTATE) ? (transition + r * NSTATE)
                                        : (output + (r - NSTATE) * NSTATE);
        float v = src[i];

        __shared__ float shm[4];
        __shared__ float shs[4];

        float m = v;
        #pragma unroll
        for (int d = 16; d; d >>= 1) m = fmaxf(m, __shfl_xor_sync(0xffffffffu, m, d));
        if ((threadIdx.x & 31) == 0) shm[threadIdx.x >> 5] = m;
        __syncthreads();
        m = fmaxf(shm[half * 2], shm[half * 2 + 1]);

        float e = expf(v - m);
        float s = e;
        #pragma unroll
        for (int d = 16; d; d >>= 1) s += __shfl_xor_sync(0xffffffffu, s, d);
        if ((threadIdx.x & 31) == 0) shs[threadIdx.x >> 5] = s;
        __syncthreads();
        s = shs[half * 2] + shs[half * 2 + 1];

        const float val = e / s;
        if (r < NSTATE) g_Tpack[(i >> 1) * 128 + r * 2 + (i & 1)] = val;
        else            g_Oexp[(r - NSTATE) * NSTATE + i] = val;
    } else {
        const int gw   = (blk - 40) * 4 + (threadIdx.x >> 5);
        const int lane = threadIdx.x & 31;
        if (gw >= VOCAB) return;
        const float* row = emb + gw * NSTATE;
        float s = expf(row[lane]) + expf(row[lane + 32]);
        #pragma unroll
        for (int d = 16; d; d >>= 1) s += __shfl_xor_sync(0xffffffffu, s, d);
        if (lane == 0) g_lse[gw] = logf(s);
    }
}

// ---------------------------------------------------------------------------
// Main: ONE WARP per batch element. Lane l owns states 2l and 2l+1.
// Champion configuration (measured 96.7us): warp-synchronous loop with
// in-loop __syncwarp, dynamic double-buffer index, exp at loop top, 3-deep
// emission prefetch, renorm every 64 steps, reuse-ordered FMA2 stream.
// ---------------------------------------------------------------------------
__global__ void __launch_bounds__(32) hmm_forward_kernel(
    const int*   __restrict__ sentences,
    const int*   __restrict__ length,
    const float* __restrict__ emb,
    float*       __restrict__ out)
{
    const int b    = blockIdx.x;
    const int lane = threadIdx.x;

    __shared__ __align__(16) float G[2][NSTATE];
    __shared__ int toks[MAXLEN];

    const int  L    = length[b];
    const int  Lm1  = L - 1;
    const int* sent = sentences + b * MAXLEN;

    // Stage tokens in SMEM (coalesced, 16 iterations max).
    for (int i = lane; i < L; i += 32) toks[i] = __ldg(&sent[i]);

    // Transition rows for states s0=2*lane, s1=2*lane+1:
    // TA[jv] = (Texp[s0][2jv], Texp[s0][2jv+1]), TB likewise for s1.
    // One LDG.128 per jv (16B per lane, coalesced).
    ull TA[NSTATE / 2], TB[NSTATE / 2];
    {
        const ulonglong2* Tp = reinterpret_cast<const ulonglong2*>(g_Tpack);
        #pragma unroll
        for (int jv = 0; jv < NSTATE / 2; ++jv) {
            const ulonglong2 p = __ldg(&Tp[jv * 32 + lane]);   // ull idx jv*64+2l
            TA[jv] = p.x;
            TB[jv] = p.y;
        }
    }

    // ---- t = 0 ----
    const int tok0 = __ldg(&sent[0]);
    const float2 raw0 = *reinterpret_cast<const float2*>(&emb[tok0 * NSTATE + 2 * lane]);
    *reinterpret_cast<float2*>(&G[0][2 * lane]) =
        make_float2(__expf(raw0.x), __expf(raw0.y));
    __syncwarp();   // G[0] + toks visible warp-wide

    // 3-deep emission-row prefetch (clamped indices: always valid loads).
    float2 r1 = *reinterpret_cast<const float2*>(&emb[toks[min(1, Lm1)] * NSTATE + 2 * lane]);
    float2 r2 = *reinterpret_cast<const float2*>(&emb[toks[min(2, Lm1)] * NSTATE + 2 * lane]);
    float2 r3 = *reinterpret_cast<const float2*>(&emb[toks[min(3, Lm1)] * NSTATE + 2 * lane]);

    float off = 0.f;
    int   buf = 0;

    for (int t = 1; t < L; ++t) {
        float eA = __expf(r1.x);
        float eB = __expf(r1.y);
        r1 = r2; r2 = r3;
        r3 = *reinterpret_cast<const float2*>(&emb[toks[min(t + 3, Lm1)] * NSTATE + 2 * lane]);

        if ((t & 63) == 0) {       // periodic renormalization (uniform branch)
            const float g0 = G[buf][0];
            float c;
            asm("rcp.approx.f32 %0, %1;" : "=f"(c) : "f"(g0));
            eA *= c;
            eB *= c;
            off += __logf(g0);
        }

        // Two 64-wide matvecs (states s0, s1) from shared G, packed f32x2.
        // Reuse-friendly order: both g.x consumers adjacent, then g.y.
        const ulonglong2* Gv = reinterpret_cast<const ulonglong2*>(G[buf]);
        ull a0 = 0ull, a1 = 0ull, b0 = 0ull, b1 = 0ull;
        #pragma unroll
        for (int jv = 0; jv < 16; ++jv) {
            const ulonglong2 g = Gv[jv];
            FMA2(a0, TA[2 * jv + 0], g.x, a0);
            FMA2(b0, TB[2 * jv + 0], g.x, b0);
            FMA2(a1, TA[2 * jv + 1], g.y, a1);
            FMA2(b1, TB[2 * jv + 1], g.y, b1);
        }
        ull as, bs;
        ADD2(as, a0, a1);
        ADD2(bs, b0, b1);
        float alo, ahi, blo, bhi;
        asm("mov.b64 {%0, %1}, %2;" : "=f"(alo), "=f"(ahi) : "l"(as));
        asm("mov.b64 {%0, %1}, %2;" : "=f"(blo), "=f"(bhi) : "l"(bs));
        const float GnA = (alo + ahi) * eA;
        const float GnB = (blo + bhi) * eB;

        buf ^= 1;
        *reinterpret_cast<float2*>(&G[buf][2 * lane]) = make_float2(GnA, GnB);
        __syncwarp();
    }

    // ---- emission-normalizer sum S = sum_{t<L} lse[tok_t] ----
    float S = 0.f;
    for (int i = lane; i < L; i += 32) S += __ldg(&g_lse[toks[i]]);
    #pragma unroll
    for (int d = 16; d; d >>= 1) S += __shfl_xor_sync(0xffffffffu, S, d);

    // ---- readout: lanes 0..15 each compute one label ----
    if (lane < NLABEL) {
        const float* O  = g_Oexp + lane * NSTATE;
        const float* Gf = G[buf];
        float a0 = 0.f, a1 = 0.f, a2 = 0.f, a3 = 0.f;
        #pragma unroll
        for (int j4 = 0; j4 < NSTATE / 4; ++j4) {
            a0 = fmaf(__ldg(&O[4 * j4 + 0]), Gf[4 * j4 + 0], a0);
            a1 = fmaf(__ldg(&O[4 * j4 + 1]), Gf[4 * j4 + 1], a1);
            a2 = fmaf(__ldg(&O[4 * j4 + 2]), Gf[4 * j4 + 2], a2);
            a3 = fmaf(__ldg(&O[4 * j4 + 3]), Gf[4 * j4 + 3], a3);
        }
        out[b * NLABEL + lane] = __logf((a0 + a1) + (a2 + a3)) + off - S;
    }
}

// ---------------------------------------------------------------------------
extern "C" void kernel_launch(void* const* d_in, const int* in_sizes, int n_in,
                              void* d_out, int out_size) {
    const int*   sentences  = nullptr;
    const int*   length     = nullptr;
    const float* emb        = nullptr;
    const float* transition = nullptr;
    const float* output     = nullptr;

    for (int i = 0; i < n_in; ++i) {
        switch (in_sizes[i]) {
            case BATCH * MAXLEN:   sentences  = (const int*)  d_in[i]; break;
            case BATCH:            length     = (const int*)  d_in[i]; break;
            case VOCAB * NSTATE:   emb        = (const float*)d_in[i]; break;
            case NSTATE * NSTATE:  transition = (const float*)d_in[i]; break;
            case NLABEL * NSTATE:  output     = (const float*)d_in[i]; break;
            default: break;
        }
    }

    prep_all_kernel<<<40 + VOCAB / 4, 128>>>(transition, output, emb);
    hmm_forward_kernel<<<BATCH, 32>>>(sentences, length, emb, (float*)d_out);
}

// round 14
// speedup vs baseline: 8.5300x; 1.1813x over previous
#include <cuda_runtime.h>
#include <cuda_bf16.h>

#define VOCAB  32000
#define NLABEL 16
#define NSTATE 64
#define BATCH  512
#define MAXLEN 512

typedef unsigned int       u32;
typedef unsigned long long ull;

// bf16x2 packed ops (sm_103a HFMA2.BF16_V2 / HADD2.BF16_V2).
#define HFMA2B(d, a, b, c) \
    asm("fma.rn.bf16x2 %0, %1, %2, %3;" : "=r"(d) : "r"(a), "r"(b), "r"(c))
#define HADD2B(d, a, b) \
    asm("add.rn.bf16x2 %0, %1, %2;" : "=r"(d) : "r"(a), "r"(b))

// Precomputed tables (device globals: no allocation allowed).
// g_Tbf16 layout (bf16 elements): element for (state r, K-index i) at
//   (i>>1)*128 + 2*r + (i&1)
// -> uint32 word w = jv*64 + r holds the bf16x2 K-pair (T[r][2jv], T[r][2jv+1]).
__device__ __align__(16) unsigned short g_Tbf16[NSTATE * NSTATE];
__device__ float g_Oexp[NLABEL * NSTATE];   // [l*64 + s] = softmax(output[l,:])[s]
__device__ float g_lse [VOCAB];             // logsumexp(emb[v,:])

// ---------------------------------------------------------------------------
// Fused prep: blocks [0,40) do row-softmax (2 rows/block: 64+16 rows total);
// blocks [40, 40+VOCAB/4) do per-vocab-row logsumexp (4 rows/block).
// ---------------------------------------------------------------------------
__global__ void prep_all_kernel(const float* __restrict__ transition,
                                const float* __restrict__ output,
                                const float* __restrict__ emb) {
    const int blk = blockIdx.x;
    if (blk < 40) {
        const int half = threadIdx.x >> 6;     // which row in this block
        const int i    = threadIdx.x & 63;     // state index within row
        const int r    = blk * 2 + half;       // global row 0..79
        const float* src = (r < NSTATE) ? (transition + r * NSTATE)
                                        : (output + (r - NSTATE) * NSTATE);
        float v = src[i];

        __shared__ float shm[4];
        __shared__ float shs[4];

        float m = v;
        #pragma unroll
        for (int d = 16; d; d >>= 1) m = fmaxf(m, __shfl_xor_sync(0xffffffffu, m, d));
        if ((threadIdx.x & 31) == 0) shm[threadIdx.x >> 5] = m;
        __syncthreads();
        m = fmaxf(shm[half * 2], shm[half * 2 + 1]);

        float e = expf(v - m);
        float s = e;
        #pragma unroll
        for (int d = 16; d; d >>= 1) s += __shfl_xor_sync(0xffffffffu, s, d);
        if ((threadIdx.x & 31) == 0) shs[threadIdx.x >> 5] = s;
        __syncthreads();
        s = shs[half * 2] + shs[half * 2 + 1];

        const float val = e / s;
        if (r < NSTATE) {
            const __nv_bfloat16 hv = __float2bfloat16(val);
            g_Tbf16[(i >> 1) * 128 + 2 * r + (i & 1)] =
                *reinterpret_cast<const unsigned short*>(&hv);
        } else {
            g_Oexp[(r - NSTATE) * NSTATE + i] = val;
        }
    } else {
        const int gw   = (blk - 40) * 4 + (threadIdx.x >> 5);
        const int lane = threadIdx.x & 31;
        if (gw >= VOCAB) return;
        const float* row = emb + gw * NSTATE;
        float s = expf(row[lane]) + expf(row[lane + 32]);
        #pragma unroll
        for (int d = 16; d; d >>= 1) s += __shfl_xor_sync(0xffffffffu, s, d);
        if (lane == 0) g_lse[gw] = logf(s);
    }
}

// ---------------------------------------------------------------------------
// Main: ONE WARP per batch element (champion skeleton). Lane l owns states
// 2l, 2l+1. Matvec in bf16x2 HFMA2 (rt=2 vs FFMA2's rt=3): T rows and the G
// exchange are bf16; emission factor, renorm, horizontal sums, and output
// stay fp32 (bf16->fp32 unpack is exact). 4 bf16x2 accumulators per state
// bound accumulation roundoff. Everything else is byte-identical in spirit
// to the 96.7us champion: in-loop __syncwarp, dynamic double-buffer index,
// exp at loop top, 3-deep emission prefetch, renorm every 64 steps.
// ---------------------------------------------------------------------------
__global__ void __launch_bounds__(32) hmm_forward_kernel(
    const int*   __restrict__ sentences,
    const int*   __restrict__ length,
    const float* __restrict__ emb,
    float*       __restrict__ out)
{
    const int b    = blockIdx.x;
    const int lane = threadIdx.x;

    __shared__ __align__(16) u32 Gs[2][NSTATE / 2];   // bf16x2 words: (G[2l],G[2l+1])
    __shared__ int toks[MAXLEN];

    const int  L    = length[b];
    const int  Lm1  = L - 1;
    const int* sent = sentences + b * MAXLEN;

    // Stage tokens in SMEM (coalesced, 16 iterations max).
    for (int i = lane; i < L; i += 32) toks[i] = __ldg(&sent[i]);

    // Transition rows for states s0=2*lane, s1=2*lane+1 as bf16x2 K-pairs:
    // TA[jv] = (T[s0][2jv], T[s0][2jv+1]), TB likewise. LDG.64 coalesced.
    u32 TA[NSTATE / 2], TB[NSTATE / 2];
    {
        const uint2* Tp = reinterpret_cast<const uint2*>(g_Tbf16);
        #pragma unroll
        for (int jv = 0; jv < NSTATE / 2; ++jv) {
            const uint2 p = __ldg(&Tp[jv * 32 + lane]);   // words jv*64+2l, +1
            TA[jv] = p.x;
            TB[jv] = p.y;
        }
    }

    // ---- t = 0 ----
    const int tok0 = __ldg(&sent[0]);
    const float2 raw0 = *reinterpret_cast<const float2*>(&emb[tok0 * NSTATE + 2 * lane]);
    {
        const __nv_bfloat162 h0 = __floats2bfloat162_rn(__expf(raw0.x), __expf(raw0.y));
        Gs[0][lane] = *reinterpret_cast<const u32*>(&h0);
    }
    __syncwarp();   // Gs[0] + toks visible warp-wide

    // 3-deep emission-row prefetch (clamped indices: always valid loads).
    float2 r1 = *reinterpret_cast<const float2*>(&emb[toks[min(1, Lm1)] * NSTATE + 2 * lane]);
    float2 r2 = *reinterpret_cast<const float2*>(&emb[toks[min(2, Lm1)] * NSTATE + 2 * lane]);
    float2 r3 = *reinterpret_cast<const float2*>(&emb[toks[min(3, Lm1)] * NSTATE + 2 * lane]);

    float off = 0.f;
    int   buf = 0;

    for (int t = 1; t < L; ++t) {
        float eA = __expf(r1.x);
        float eB = __expf(r1.y);
        r1 = r2; r2 = r3;
        r3 = *reinterpret_cast<const float2*>(&emb[toks[min(t + 3, Lm1)] * NSTATE + 2 * lane]);

        if ((t & 63) == 0) {       // periodic renormalization (uniform branch)
            const float g0 = __uint_as_float(Gs[buf][0] << 16);   // bf16 lo -> fp32
            float c;
            asm("rcp.approx.f32 %0, %1;" : "=f"(c) : "f"(g0));
            eA *= c;
            eB *= c;
            off += __logf(g0);
        }

        // Two 64-wide matvecs in bf16x2: 8 LDS.128 + 64 HFMA2 (rt=2).
        // 4 accumulators per state bound bf16 accumulation roundoff.
        const uint4* Gv = reinterpret_cast<const uint4*>(Gs[buf]);
        u32 a0 = 0u, a1 = 0u, a2 = 0u, a3 = 0u;
        u32 b0 = 0u, b1 = 0u, b2 = 0u, b3 = 0u;
        #pragma unroll
        for (int q = 0; q < 8; ++q) {
            const uint4 g = Gv[q];
            HFMA2B(a0, TA[4 * q + 0], g.x, a0);
            HFMA2B(b0, TB[4 * q + 0], g.x, b0);
            HFMA2B(a1, TA[4 * q + 1], g.y, a1);
            HFMA2B(b1, TB[4 * q + 1], g.y, b1);
            HFMA2B(a2, TA[4 * q + 2], g.z, a2);
            HFMA2B(b2, TB[4 * q + 2], g.z, b2);
            HFMA2B(a3, TA[4 * q + 3], g.w, a3);
            HFMA2B(b3, TB[4 * q + 3], g.w, b3);
        }
        u32 sa, sb, u, v;
        HADD2B(u, a0, a1);
        HADD2B(v, a2, a3);
        HADD2B(sa, u, v);
        HADD2B(u, b0, b1);
        HADD2B(v, b2, b3);
        HADD2B(sb, u, v);
        // Horizontal pair-sum + emission multiply in fp32 (exact unpack).
        const float GnA = (__uint_as_float(sa << 16) +
                           __uint_as_float(sa & 0xffff0000u)) * eA;
        const float GnB = (__uint_as_float(sb << 16) +
                           __uint_as_float(sb & 0xffff0000u)) * eB;

        buf ^= 1;
        const __nv_bfloat162 hn = __floats2bfloat162_rn(GnA, GnB);
        Gs[buf][lane] = *reinterpret_cast<const u32*>(&hn);
        __syncwarp();
    }

    // ---- emission-normalizer sum S = sum_{t<L} lse[tok_t] ----
    float S = 0.f;
    for (int i = lane; i < L; i += 32) S += __ldg(&g_lse[toks[i]]);
    #pragma unroll
    for (int d = 16; d; d >>= 1) S += __shfl_xor_sync(0xffffffffu, S, d);

    // ---- readout: lanes 0..15 each compute one label (fp32) ----
    if (lane < NLABEL) {
        const float* O = g_Oexp + lane * NSTATE;
        const u32*  Gf = Gs[buf];
        float acc0 = 0.f, acc1 = 0.f;
        #pragma unroll
        for (int j = 0; j < NSTATE / 2; ++j) {
            const u32 wv = Gf[j];
            const float glo = __uint_as_float(wv << 16);
            const float ghi = __uint_as_float(wv & 0xffff0000u);
            acc0 = fmaf(__ldg(&O[2 * j + 0]), glo, acc0);
            acc1 = fmaf(__ldg(&O[2 * j + 1]), ghi, acc1);
        }
        out[b * NLABEL + lane] = __logf(acc0 + acc1) + off - S;
    }
}

// ---------------------------------------------------------------------------
extern "C" void kernel_launch(void* const* d_in, const int* in_sizes, int n_in,
                              void* d_out, int out_size) {
    const int*   sentences  = nullptr;
    const int*   length     = nullptr;
    const float* emb        = nullptr;
    const float* transition = nullptr;
    const float* output     = nullptr;

    for (int i = 0; i < n_in; ++i) {
        switch (in_sizes[i]) {
            case BATCH * MAXLEN:   sentences  = (const int*)  d_in[i]; break;
            case BATCH:            length     = (const int*)  d_in[i]; break;
            case VOCAB * NSTATE:   emb        = (const float*)d_in[i]; break;
            case NSTATE * NSTATE:  transition = (const float*)d_in[i]; break;
            case NLABEL * NSTATE:  output     = (const float*)d_in[i]; break;
            default: break;
        }
    }

    prep_all_kernel<<<40 + VOCAB / 4, 128>>>(transition, output, emb);
    hmm_forward_kernel<<<BATCH, 32>>>(sentences, length, emb, (float*)d_out);
}